// round 1
// baseline (speedup 1.0000x reference)
#include <cuda_runtime.h>
#include <math.h>

// ---------------------------------------------------------------------------
// Problem constants
// ---------------------------------------------------------------------------
#define B 4
#define C 64
#define IMGH 48
#define IMGW 48
#define HW 2304                 // 48*48
#define NPIX 589824             // B*C*HW
#define CV 24                   // 3 * (C/8) value columns

// ---------------------------------------------------------------------------
// Device scratch (no cudaMalloc allowed)
// ---------------------------------------------------------------------------
__device__ float g_buf1[NPIX];
__device__ float g_buf2[NPIX];
__device__ float g_f[3 * NPIX];          // [3][B][64][2304] final features
__device__ float g_r[12 * HW];           // [3][B][2304]  squared norms
__device__ float g_V[B * HW * CV];       // [B][2304][24] stacked values
__device__ float g_O[12 * HW * CV];      // [3][B][2304][24]  a_j @ V
__device__ float g_edge[B * HW];         // sobel magnitude of x3
__device__ float g_scale[9 * 64];        // folded BN scale per block
__device__ float g_shift[9 * 64];        // folded BN shift per block

// ---------------------------------------------------------------------------
// 0) Fold conv bias + BN into per-channel scale/shift
//    y = conv*s + shift ; s = g/sqrt(v+eps) ; shift = (bias - m)*s + be
// ---------------------------------------------------------------------------
__global__ void prep_kernel(const float* __restrict__ bc1, const float* __restrict__ bc2,
                            const float* __restrict__ bc3,
                            const float* __restrict__ bnf_g, const float* __restrict__ bnf_b,
                            const float* __restrict__ bnf_m, const float* __restrict__ bnf_v,
                            const float* __restrict__ bm,
                            const float* __restrict__ bnm_g, const float* __restrict__ bnm_b,
                            const float* __restrict__ bnm_m, const float* __restrict__ bnm_v)
{
    int t = threadIdx.x;
    if (t >= 576) return;
    int bi = t >> 6, c = t & 63;
    float bias, g, be, m, v;
    if (bi < 3) {
        bias = (bi == 0) ? bc1[c] : (bi == 1) ? bc2[c] : bc3[c];
        g = bnf_g[bi * 64 + c]; be = bnf_b[bi * 64 + c];
        m = bnf_m[bi * 64 + c]; v = bnf_v[bi * 64 + c];
    } else {
        int r = bi - 3;
        bias = bm[r * 64 + c];
        g = bnm_g[r * 64 + c]; be = bnm_b[r * 64 + c];
        m = bnm_m[r * 64 + c]; v = bnm_v[r * 64 + c];
    }
    float s = g * rsqrtf(v + 1e-5f);
    g_scale[t] = s;
    g_shift[t] = (bias - m) * s + be;
}

// ---------------------------------------------------------------------------
// 1) Sobel edge on raw x3 (single channel)
// ---------------------------------------------------------------------------
__global__ void edge_kernel(const float* __restrict__ x3)
{
    int idx = blockIdx.x * 256 + threadIdx.x;
    if (idx >= B * HW) return;
    int b = idx / HW, p = idx % HW;
    int h = p / IMGW, w = p % IMGW;
    const float* X = x3 + b * HW;
    float ex = 0.f, ey = 0.f;
    const float KX[9] = {-1.f, 0.f, 1.f, -2.f, 0.f, 2.f, -1.f, 0.f, 1.f};
    const float KY[9] = {-1.f, -2.f, -1.f, 0.f, 0.f, 0.f, 1.f, 2.f, 1.f};
#pragma unroll
    for (int kh = 0; kh < 3; kh++) {
        int gh = h + kh - 1;
        if (gh < 0 || gh >= IMGH) continue;
#pragma unroll
        for (int kw = 0; kw < 3; kw++) {
            int gw = w + kw - 1;
            if (gw < 0 || gw >= IMGW) continue;
            float xv = X[gh * IMGW + gw];
            ex += xv * KX[kh * 3 + kw];
            ey += xv * KY[kh * 3 + kw];
        }
    }
    g_edge[idx] = sqrtf(ex * ex + ey * ey);
}

// ---------------------------------------------------------------------------
// 2) 3x3 conv (correlation, SAME) + folded BN + LeakyReLU(0.01)
//    grid: (12 row-strips of 4, 4 cout-groups of 16, B)   block: 128
//    Each thread: 6 pixels x 4 couts = 24 accumulators.
// ---------------------------------------------------------------------------
#define CIN_CHUNK 16
__global__ __launch_bounds__(128) void conv_kernel(const float* __restrict__ in,
                                                   const float* __restrict__ W,
                                                   int Cin, int bn_idx,
                                                   float* __restrict__ out)
{
    __shared__ float in_s[CIN_CHUNK][6][50];       // 4 rows + halo, 48 cols + halo
    __shared__ float w_s[CIN_CHUNK * 9 * 16];      // [ci][tap][co16]

    const int strip = blockIdx.x, cog = blockIdx.y, b = blockIdx.z;
    const int r0 = strip * 4;
    const int t = threadIdx.x;
    const int cg = t & 3;            // co sub-group (4 couts)
    const int pg = t >> 2;           // 0..31 pixel group (6 cols)
    const int prow = pg >> 3;        // 0..3
    const int pcol0 = (pg & 7) * 6;  // 0,6,...,42
    const int cg4 = cg * 4;

    float acc[6][4];
#pragma unroll
    for (int i = 0; i < 6; i++)
#pragma unroll
        for (int j = 0; j < 4; j++) acc[i][j] = 0.f;

    for (int c0 = 0; c0 < Cin; c0 += CIN_CHUNK) {
        int cc = min(CIN_CHUNK, Cin - c0);
        // load input strip with halo (zero padded)
        for (int idx = t; idx < cc * 300; idx += 128) {
            int ci = idx / 300;
            int rem = idx % 300;
            int rr = rem / 50, ccol = rem % 50;
            int gr = r0 + rr - 1, gcol = ccol - 1;
            float v = 0.f;
            if (gr >= 0 && gr < IMGH && gcol >= 0 && gcol < IMGW)
                v = in[((b * Cin + c0 + ci) * IMGH + gr) * IMGW + gcol];
            in_s[ci][rr][ccol] = v;
        }
        // load weights -> [ci][tap][co]
        for (int idx = t; idx < cc * 9 * 16; idx += 128) {
            int co = idx & 15;
            int tmp = idx >> 4;
            int tap = tmp % 9;
            int ci = tmp / 9;
            w_s[idx] = W[((cog * 16 + co) * Cin + c0 + ci) * 9 + tap];
        }
        __syncthreads();

        for (int ci = 0; ci < cc; ++ci) {
            float x[3][8];
#pragma unroll
            for (int rr = 0; rr < 3; rr++)
#pragma unroll
                for (int k = 0; k < 8; k++)
                    x[rr][k] = in_s[ci][prow + rr][pcol0 + k];
#pragma unroll
            for (int tr = 0; tr < 3; tr++) {
#pragma unroll
                for (int tc = 0; tc < 3; tc++) {
                    const float* wp = &w_s[(ci * 9 + tr * 3 + tc) * 16 + cg4];
                    float w0 = wp[0], w1 = wp[1], w2 = wp[2], w3 = wp[3];
#pragma unroll
                    for (int px = 0; px < 6; px++) {
                        float xv = x[tr][px + tc];
                        acc[px][0] += xv * w0;
                        acc[px][1] += xv * w1;
                        acc[px][2] += xv * w2;
                        acc[px][3] += xv * w3;
                    }
                }
            }
        }
        __syncthreads();
    }

#pragma unroll
    for (int co = 0; co < 4; co++) {
        int coo = cog * 16 + cg4 + co;
        float s = g_scale[bn_idx * 64 + coo];
        float sh = g_shift[bn_idx * 64 + coo];
#pragma unroll
        for (int px = 0; px < 6; px++) {
            float y = acc[px][co] * s + sh;
            y = (y > 0.f) ? y : 0.01f * y;
            out[((b * C + coo) * IMGH + r0 + prow) * IMGW + pcol0 + px] = y;
        }
    }
}

// ---------------------------------------------------------------------------
// 3) Per-pixel squared norm r and 1x1 value projection (stacked, +bias)
//    grid: (9 pixel chunks, 3 branches, B)  block: 256
// ---------------------------------------------------------------------------
__global__ void valr_kernel(const float* __restrict__ Wv, const float* __restrict__ bv)
{
    __shared__ float wv_s[512];   // [8][64]
    int t = threadIdx.x;
    int j = blockIdx.y, b = blockIdx.z;
    for (int i = t; i < 512; i += 256) wv_s[i] = Wv[i];
    __syncthreads();

    int p = blockIdx.x * 256 + t;
    const float* F = g_f + (j * 4 + b) * C * HW + p;
    float r = 0.f;
    float v[8] = {0, 0, 0, 0, 0, 0, 0, 0};
#pragma unroll 8
    for (int c = 0; c < C; c++) {
        float x = F[c * HW];
        r += x * x;
#pragma unroll
        for (int cv = 0; cv < 8; cv++) v[cv] += wv_s[cv * 64 + c] * x;
    }
    g_r[(j * 4 + b) * HW + p] = r;
#pragma unroll
    for (int cv = 0; cv < 8; cv++)
        g_V[(b * HW + p) * CV + j * 8 + cv] = v[cv] + bv[cv];
}

// ---------------------------------------------------------------------------
// 4) Fused similarity-attention:  O_j = exp(-d2/(2*sigma_j^2)) @ V
//    Never materializes the [2304,2304] matrices.
//    grid: (18 row tiles of 128, 3 branches, B)  block: 256, dynamic smem
// ---------------------------------------------------------------------------
#define TM 128
#define TN 64
#define ASTRIDE 68

__global__ __launch_bounds__(256, 2) void attn_kernel(const float* __restrict__ gammas)
{
    extern __shared__ float sm[];
    float* Fr  = sm;                       // [64][TM]
    float* Fc  = Fr + C * TM;              // [64][TN]
    float* As  = Fc + C * TN;              // [TM][ASTRIDE]
    float* Vs  = As + TM * ASTRIDE;        // [TN][CV]
    float* r_r = Vs + TN * CV;             // [TM]
    float* r_c = r_r + TM;                 // [TN]

    const int tile = blockIdx.x, j = blockIdx.y, b = blockIdx.z;
    const int m0 = tile * TM;
    const int t = threadIdx.x;

    const float* F  = g_f + (j * 4 + b) * C * HW;
    const float* Rj = g_r + (j * 4 + b) * HW;

    float sg = gammas[j];
    float inv2s = 1.0f / (2.0f * sg * sg);

    // Load the 128-row feature block once
    for (int idx = t; idx < C * TM; idx += 256) {
        int c = idx / TM, i = idx % TM;
        Fr[c * TM + i] = F[c * HW + m0 + i];
    }
    if (t < TM) r_r[t] = Rj[m0 + t];

    // Gram-phase thread mapping (128x64 tile, 8x4 per thread)
    const int itile = t >> 4, ntile = t & 15;
    const int i0 = itile * 8, n0 = ntile * 4;
    // second-GEMM mapping (4 rows x 3 cols per thread)
    const int rg = t >> 3;   // 0..31
    const int cq = t & 7;    // 0..7

    float O[4][3];
#pragma unroll
    for (int a = 0; a < 4; a++)
#pragma unroll
        for (int q = 0; q < 3; q++) O[a][q] = 0.f;

    for (int nb = 0; nb < HW; nb += TN) {
        __syncthreads();  // previous iteration done with Fc / As / Vs
        for (int idx = t; idx < C * TN; idx += 256) {
            int c = idx / TN, n = idx % TN;
            Fc[c * TN + n] = F[c * HW + nb + n];
        }
        for (int idx = t; idx < TN * CV; idx += 256)
            Vs[idx] = g_V[(b * HW + nb) * CV + idx];
        if (t < TN) r_c[t] = Rj[nb + t];
        __syncthreads();

        // ---- Gram tile (fp32, exact like reference) ----
        float S[8][4];
#pragma unroll
        for (int a = 0; a < 8; a++)
#pragma unroll
            for (int q = 0; q < 4; q++) S[a][q] = 0.f;

#pragma unroll 4
        for (int c = 0; c < C; c++) {
            float4 xr0 = *(const float4*)&Fr[c * TM + i0];
            float4 xr1 = *(const float4*)&Fr[c * TM + i0 + 4];
            float4 xc4 = *(const float4*)&Fc[c * TN + n0];
            float xr[8] = {xr0.x, xr0.y, xr0.z, xr0.w, xr1.x, xr1.y, xr1.z, xr1.w};
            float xcc[4] = {xc4.x, xc4.y, xc4.z, xc4.w};
#pragma unroll
            for (int a = 0; a < 8; a++)
#pragma unroll
                for (int q = 0; q < 4; q++)
                    S[a][q] += xr[a] * xcc[q];
        }
        // ---- d2 -> exp -> stage tile ----
#pragma unroll
        for (int a = 0; a < 8; a++) {
            float ri = r_r[i0 + a];
#pragma unroll
            for (int q = 0; q < 4; q++) {
                float d2 = ri + r_c[n0 + q] - 2.f * S[a][q];
                d2 = fmaxf(d2, 0.f);
                As[(i0 + a) * ASTRIDE + n0 + q] = __expf(-d2 * inv2s);
            }
        }
        __syncthreads();

        // ---- A_tile @ V_chunk accumulate ----
#pragma unroll 4
        for (int n = 0; n < TN; n++) {
            float a0 = As[(rg * 4 + 0) * ASTRIDE + n];
            float a1 = As[(rg * 4 + 1) * ASTRIDE + n];
            float a2 = As[(rg * 4 + 2) * ASTRIDE + n];
            float a3 = As[(rg * 4 + 3) * ASTRIDE + n];
            float v0 = Vs[n * CV + cq * 3 + 0];
            float v1 = Vs[n * CV + cq * 3 + 1];
            float v2 = Vs[n * CV + cq * 3 + 2];
            O[0][0] += a0 * v0; O[0][1] += a0 * v1; O[0][2] += a0 * v2;
            O[1][0] += a1 * v0; O[1][1] += a1 * v1; O[1][2] += a1 * v2;
            O[2][0] += a2 * v0; O[2][1] += a2 * v1; O[2][2] += a2 * v2;
            O[3][0] += a3 * v0; O[3][1] += a3 * v1; O[3][2] += a3 * v2;
        }
    }

#pragma unroll
    for (int a = 0; a < 4; a++)
#pragma unroll
        for (int q = 0; q < 3; q++)
            g_O[((j * 4 + b) * HW + m0 + rg * 4 + a) * CV + cq * 3 + q] = O[a][q];
}

// ---------------------------------------------------------------------------
// 5) Combine:  att_k = gk * sum_j coef_jk * O_j[:, k*8:(k+1)*8]
//    out_k = f_k * (att_k @ Wo^T + bo) + edge
//    grid: (9 pixel chunks, 3 outputs, B)  block: 256
// ---------------------------------------------------------------------------
__global__ void combine_kernel(const float* __restrict__ Wo, const float* __restrict__ bo,
                               const float* __restrict__ gammas, float* __restrict__ out)
{
    __shared__ float wo_s[512];   // [64][8]
    __shared__ float bo_s[64];
    int t = threadIdx.x;
    for (int i = t; i < 512; i += 256) wo_s[i] = Wo[i];
    if (t < 64) bo_s[t] = bo[t];
    __syncthreads();

    int k = blockIdx.y, b = blockIdx.z;
    int p = blockIdx.x * 256 + t;

    float g6 = gammas[6], g7 = gammas[7], g8 = gammas[8];
    float c1, c2, c3, gk;
    if (k == 0)      { c1 = g6;       c2 = g7 + 1.f; c3 = g8 + 1.f; gk = gammas[3]; }
    else if (k == 1) { c1 = g6 + 1.f; c2 = g7;       c3 = g8 + 1.f; gk = gammas[4]; }
    else             { c1 = g6 + 1.f; c2 = g7 + 1.f; c3 = g8;       gk = gammas[5]; }

    const float* O0 = g_O + ((0 + b) * HW + p) * CV + k * 8;
    const float* O1 = g_O + ((4 + b) * HW + p) * CV + k * 8;
    const float* O2 = g_O + ((8 + b) * HW + p) * CV + k * 8;
    float att[8];
#pragma unroll
    for (int c = 0; c < 8; c++)
        att[c] = gk * (c1 * O0[c] + c2 * O1[c] + c3 * O2[c]);

    float e = g_edge[b * HW + p];
    const float* F = g_f + (k * 4 + b) * C * HW + p;
    float* op = out + k * NPIX + b * C * HW + p;
#pragma unroll 4
    for (int co = 0; co < C; co++) {
        float y = bo_s[co];
#pragma unroll
        for (int c = 0; c < 8; c++) y += wo_s[co * 8 + c] * att[c];
        op[co * HW] = F[co * HW] * y + e;
    }
}

// ---------------------------------------------------------------------------
// Host launcher (graph-capturable: kernel launches only)
// ---------------------------------------------------------------------------
extern "C" void kernel_launch(void* const* d_in, const int* in_sizes, int n_in,
                              void* d_out, int out_size)
{
    const float* x1    = (const float*)d_in[0];
    const float* x2    = (const float*)d_in[1];
    const float* x3    = (const float*)d_in[2];
    const float* Wc1   = (const float*)d_in[3];
    const float* bc1   = (const float*)d_in[4];
    const float* Wc2   = (const float*)d_in[5];
    const float* bc2   = (const float*)d_in[6];
    const float* Wc3   = (const float*)d_in[7];
    const float* bc3   = (const float*)d_in[8];
    const float* bnf_g = (const float*)d_in[9];
    const float* bnf_b = (const float*)d_in[10];
    const float* bnf_m = (const float*)d_in[11];
    const float* bnf_v = (const float*)d_in[12];
    const float* Wm    = (const float*)d_in[13];
    const float* bm    = (const float*)d_in[14];
    const float* bnm_g = (const float*)d_in[15];
    const float* bnm_b = (const float*)d_in[16];
    const float* bnm_m = (const float*)d_in[17];
    const float* bnm_v = (const float*)d_in[18];
    const float* Wv    = (const float*)d_in[19];
    const float* bv    = (const float*)d_in[20];
    const float* Wo    = (const float*)d_in[21];
    const float* bo    = (const float*)d_in[22];
    const float* gam   = (const float*)d_in[23];
    float* out = (float*)d_out;

    float *buf1, *buf2, *fbase;
    cudaGetSymbolAddress((void**)&buf1, g_buf1);
    cudaGetSymbolAddress((void**)&buf2, g_buf2);
    cudaGetSymbolAddress((void**)&fbase, g_f);

    const int WMROW = 64 * 64 * 9;
    const size_t ATTN_SMEM = (size_t)(C * TM + C * TN + TM * ASTRIDE + TN * CV + TM + TN) * 4;
    cudaFuncSetAttribute(attn_kernel, cudaFuncAttributeMaxDynamicSharedMemorySize, (int)ATTN_SMEM);

    prep_kernel<<<1, 576>>>(bc1, bc2, bc3, bnf_g, bnf_b, bnf_m, bnf_v,
                            bm, bnm_g, bnm_b, bnm_m, bnm_v);
    edge_kernel<<<(B * HW + 255) / 256, 256>>>(x3);

    dim3 cgrid(12, 4, B);
    // branch 1
    conv_kernel<<<cgrid, 128>>>(x1, Wc1, 144, 0, buf1);
    conv_kernel<<<cgrid, 128>>>(buf1, Wm + 0 * WMROW, 64, 3, buf2);
    conv_kernel<<<cgrid, 128>>>(buf2, Wm + 1 * WMROW, 64, 4, fbase + 0 * NPIX);
    // branch 2
    conv_kernel<<<cgrid, 128>>>(x2, Wc2, 21, 1, buf1);
    conv_kernel<<<cgrid, 128>>>(buf1, Wm + 2 * WMROW, 64, 5, buf2);
    conv_kernel<<<cgrid, 128>>>(buf2, Wm + 3 * WMROW, 64, 6, fbase + 1 * NPIX);
    // branch 3
    conv_kernel<<<cgrid, 128>>>(x3, Wc3, 1, 2, buf1);
    conv_kernel<<<cgrid, 128>>>(buf1, Wm + 4 * WMROW, 64, 7, buf2);
    conv_kernel<<<cgrid, 128>>>(buf2, Wm + 5 * WMROW, 64, 8, fbase + 2 * NPIX);

    valr_kernel<<<dim3(9, 3, B), 256>>>(Wv, bv);
    attn_kernel<<<dim3(HW / TM, 3, B), 256, ATTN_SMEM>>>(gam);
    combine_kernel<<<dim3(9, 3, B), 256>>>(Wo, bo, gam, out);
}

// round 2
// speedup vs baseline: 1.3718x; 1.3718x over previous
#include <cuda_runtime.h>
#include <math.h>

// ---------------------------------------------------------------------------
// Problem constants
// ---------------------------------------------------------------------------
#define B 4
#define C 64
#define IMGH 48
#define IMGW 48
#define HW 2304                 // 48*48
#define NPIX 589824             // B*C*HW
#define CV 24                   // 3 * (C/8) value columns

// ---------------------------------------------------------------------------
// Device scratch (no cudaMalloc allowed)
// ---------------------------------------------------------------------------
__device__ float g_buf1[3 * NPIX];       // [3][B][64][HW] layer-1 out
__device__ float g_buf2[3 * NPIX];       // [3][B][64][HW] layer-2 out
__device__ float g_f[3 * NPIX];          // [3][B][64][HW] final features
__device__ float g_r[12 * HW];           // [3][B][2304]  squared norms
__device__ float g_V[B * HW * CV];       // [B][2304][24] stacked values
__device__ float g_O[2 * 12 * HW * CV];  // [split][3][B][2304][24]  a_j @ V (partial)
__device__ float g_edge[B * HW];         // sobel magnitude of x3
__device__ float g_scale[9 * 64];        // folded BN scale per block
__device__ float g_shift[9 * 64];        // folded BN shift per block

// ---------------------------------------------------------------------------
// 0) Fold conv bias + BN into per-channel scale/shift
// ---------------------------------------------------------------------------
__global__ void prep_kernel(const float* __restrict__ bc1, const float* __restrict__ bc2,
                            const float* __restrict__ bc3,
                            const float* __restrict__ bnf_g, const float* __restrict__ bnf_b,
                            const float* __restrict__ bnf_m, const float* __restrict__ bnf_v,
                            const float* __restrict__ bm,
                            const float* __restrict__ bnm_g, const float* __restrict__ bnm_b,
                            const float* __restrict__ bnm_m, const float* __restrict__ bnm_v)
{
    int t = threadIdx.x;
    if (t >= 576) return;
    int bi = t >> 6, c = t & 63;
    float bias, g, be, m, v;
    if (bi < 3) {
        bias = (bi == 0) ? bc1[c] : (bi == 1) ? bc2[c] : bc3[c];
        g = bnf_g[bi * 64 + c]; be = bnf_b[bi * 64 + c];
        m = bnf_m[bi * 64 + c]; v = bnf_v[bi * 64 + c];
    } else {
        int r = bi - 3;
        bias = bm[r * 64 + c];
        g = bnm_g[r * 64 + c]; be = bnm_b[r * 64 + c];
        m = bnm_m[r * 64 + c]; v = bnm_v[r * 64 + c];
    }
    float s = g * rsqrtf(v + 1e-5f);
    g_scale[t] = s;
    g_shift[t] = (bias - m) * s + be;
}

// ---------------------------------------------------------------------------
// 1) Sobel edge on raw x3 (single channel)
// ---------------------------------------------------------------------------
__global__ void edge_kernel(const float* __restrict__ x3)
{
    int idx = blockIdx.x * 256 + threadIdx.x;
    if (idx >= B * HW) return;
    int b = idx / HW, p = idx % HW;
    int h = p / IMGW, w = p % IMGW;
    const float* X = x3 + b * HW;
    float ex = 0.f, ey = 0.f;
    const float KX[9] = {-1.f, 0.f, 1.f, -2.f, 0.f, 2.f, -1.f, 0.f, 1.f};
    const float KY[9] = {-1.f, -2.f, -1.f, 0.f, 0.f, 0.f, 1.f, 2.f, 1.f};
#pragma unroll
    for (int kh = 0; kh < 3; kh++) {
        int gh = h + kh - 1;
        if (gh < 0 || gh >= IMGH) continue;
#pragma unroll
        for (int kw = 0; kw < 3; kw++) {
            int gw = w + kw - 1;
            if (gw < 0 || gw >= IMGW) continue;
            float xv = X[gh * IMGW + gw];
            ex += xv * KX[kh * 3 + kw];
            ey += xv * KY[kh * 3 + kw];
        }
    }
    g_edge[idx] = sqrtf(ex * ex + ey * ey);
}

// ---------------------------------------------------------------------------
// 2) 3x3 conv (SAME) + folded BN + LeakyReLU(0.01), shared body
//    per block: 4-row strip x 48 cols x 16 couts, 128 threads
//    per thread: 6 pixels x 4 couts
// ---------------------------------------------------------------------------
#define CIN_CHUNK 16
__device__ __forceinline__ void conv_body(const float* __restrict__ in,
                                          const float* __restrict__ W,
                                          int Cin, int bn_idx, int b,
                                          float* __restrict__ out)
{
    __shared__ float in_s[CIN_CHUNK][6][50];               // 4 rows + halo
    __shared__ __align__(16) float w_s[CIN_CHUNK * 9 * 16];

    const int strip = blockIdx.x, cog = blockIdx.y;
    const int r0 = strip * 4;
    const int t = threadIdx.x;
    const int cg = t & 3;            // co sub-group (4 couts)
    const int pg = t >> 2;           // 0..31 pixel group (6 cols)
    const int prow = pg >> 3;        // 0..3
    const int pcol0 = (pg & 7) * 6;  // 0,6,...,42
    const int cg4 = cg * 4;

    float acc[6][4];
#pragma unroll
    for (int i = 0; i < 6; i++)
#pragma unroll
        for (int j = 0; j < 4; j++) acc[i][j] = 0.f;

    for (int c0 = 0; c0 < Cin; c0 += CIN_CHUNK) {
        int cc = min(CIN_CHUNK, Cin - c0);
        for (int idx = t; idx < cc * 300; idx += 128) {
            int ci = idx / 300;
            int rem = idx % 300;
            int rr = rem / 50, ccol = rem % 50;
            int gr = r0 + rr - 1, gcol = ccol - 1;
            float v = 0.f;
            if (gr >= 0 && gr < IMGH && gcol >= 0 && gcol < IMGW)
                v = in[((b * Cin + c0 + ci) * IMGH + gr) * IMGW + gcol];
            in_s[ci][rr][ccol] = v;
        }
        for (int idx = t; idx < cc * 9 * 16; idx += 128) {
            int co = idx & 15;
            int tmp = idx >> 4;
            int tap = tmp % 9;
            int ci = tmp / 9;
            w_s[idx] = W[((cog * 16 + co) * Cin + c0 + ci) * 9 + tap];
        }
        __syncthreads();

        for (int ci = 0; ci < cc; ++ci) {
            float x[3][8];
#pragma unroll
            for (int rr = 0; rr < 3; rr++)
#pragma unroll
                for (int k = 0; k < 8; k++)
                    x[rr][k] = in_s[ci][prow + rr][pcol0 + k];
#pragma unroll
            for (int tr = 0; tr < 3; tr++) {
#pragma unroll
                for (int tc = 0; tc < 3; tc++) {
                    float4 w4 = *(const float4*)&w_s[(ci * 9 + tr * 3 + tc) * 16 + cg4];
#pragma unroll
                    for (int px = 0; px < 6; px++) {
                        float xv = x[tr][px + tc];
                        acc[px][0] += xv * w4.x;
                        acc[px][1] += xv * w4.y;
                        acc[px][2] += xv * w4.z;
                        acc[px][3] += xv * w4.w;
                    }
                }
            }
        }
        __syncthreads();
    }

#pragma unroll
    for (int co = 0; co < 4; co++) {
        int coo = cog * 16 + cg4 + co;
        float s = g_scale[bn_idx * 64 + coo];
        float sh = g_shift[bn_idx * 64 + coo];
#pragma unroll
        for (int px = 0; px < 6; px++) {
            float y = acc[px][co] * s + sh;
            y = (y > 0.f) ? y : 0.01f * y;
            out[((b * C + coo) * IMGH + r0 + prow) * IMGW + pcol0 + px] = y;
        }
    }
}

// Layer 1: all 3 branches in one launch.  grid (12, 4, B*3)
__global__ __launch_bounds__(128) void conv1_kernel(const float* __restrict__ x1,
                                                    const float* __restrict__ x2,
                                                    const float* __restrict__ x3,
                                                    const float* __restrict__ W1,
                                                    const float* __restrict__ W2,
                                                    const float* __restrict__ W3,
                                                    float* __restrict__ out)
{
    int z = blockIdx.z;
    int b = z & 3, br = z >> 2;
    const float* in = (br == 0) ? x1 : (br == 1) ? x2 : x3;
    const float* W  = (br == 0) ? W1 : (br == 1) ? W2 : W3;
    int Cin         = (br == 0) ? 144 : (br == 1) ? 21 : 1;
    conv_body(in, W, Cin, br, b, out + br * NPIX);
}

// Layers 2/3: all 3 branches.  layer = 0 or 1.  grid (12, 4, B*3)
__global__ __launch_bounds__(128) void convm_kernel(const float* __restrict__ inbase,
                                                    const float* __restrict__ Wm,
                                                    int layer,
                                                    float* __restrict__ outbase)
{
    int z = blockIdx.z;
    int b = z & 3, br = z >> 2;
    int wi = br * 2 + layer;
    const int WMROW = 64 * 64 * 9;
    conv_body(inbase + br * NPIX, Wm + wi * WMROW, 64, 3 + wi, b, outbase + br * NPIX);
}

// ---------------------------------------------------------------------------
// 3) Per-pixel squared norm r and 1x1 value projection (stacked, +bias)
// ---------------------------------------------------------------------------
__global__ void valr_kernel(const float* __restrict__ Wv, const float* __restrict__ bv)
{
    __shared__ float wv_s[512];   // [8][64]
    int t = threadIdx.x;
    int j = blockIdx.y, b = blockIdx.z;
    for (int i = t; i < 512; i += 256) wv_s[i] = Wv[i];
    __syncthreads();

    int p = blockIdx.x * 256 + t;
    const float* F = g_f + (j * 4 + b) * C * HW + p;
    float r = 0.f;
    float v[8] = {0, 0, 0, 0, 0, 0, 0, 0};
#pragma unroll 8
    for (int c = 0; c < C; c++) {
        float x = F[c * HW];
        r += x * x;
#pragma unroll
        for (int cv = 0; cv < 8; cv++) v[cv] += wv_s[cv * 64 + c] * x;
    }
    g_r[(j * 4 + b) * HW + p] = r;
#pragma unroll
    for (int cv = 0; cv < 8; cv++)
        g_V[(b * HW + p) * CV + j * 8 + cv] = v[cv] + bv[cv];
}

// ---------------------------------------------------------------------------
// 4) Fused similarity-attention:  O_j = exp(-d2/(2*sigma_j^2)) @ V
//    Column-split x2 for occupancy: each block covers half the key columns.
//    grid: (18 tiles * 2 splits, 3 branches, B)  block 256, dyn smem
// ---------------------------------------------------------------------------
#define TM 128
#define TN 64
#define ASTRIDE 68
#define NSPLIT 2
#define COLS_PER_SPLIT (HW / NSPLIT)

__global__ __launch_bounds__(256, 2) void attn_kernel(const float* __restrict__ gammas)
{
    extern __shared__ float sm[];
    float* Fr  = sm;                       // [64][TM]
    float* Fc  = Fr + C * TM;              // [64][TN]
    float* As  = Fc + C * TN;              // [TM][ASTRIDE]
    float* Vs  = As + TM * ASTRIDE;        // [TN][CV]
    float* r_r = Vs + TN * CV;             // [TM]
    float* r_c = r_r + TM;                 // [TN]

    const int s = blockIdx.x & 1;
    const int tile = blockIdx.x >> 1;
    const int j = blockIdx.y, b = blockIdx.z;
    const int m0 = tile * TM;
    const int t = threadIdx.x;

    const float* F  = g_f + (j * 4 + b) * C * HW;
    const float* Rj = g_r + (j * 4 + b) * HW;

    float sg = gammas[j];
    float inv2s = 1.0f / (2.0f * sg * sg);

    for (int idx = t; idx < C * TM; idx += 256) {
        int c = idx / TM, i = idx % TM;
        Fr[c * TM + i] = F[c * HW + m0 + i];
    }
    if (t < TM) r_r[t] = Rj[m0 + t];

    const int itile = t >> 4, ntile = t & 15;
    const int i0 = itile * 8, n0 = ntile * 4;
    const int rg = t >> 3;   // 0..31
    const int cq = t & 7;    // 0..7

    float O[4][3];
#pragma unroll
    for (int a = 0; a < 4; a++)
#pragma unroll
        for (int q = 0; q < 3; q++) O[a][q] = 0.f;

    const int nb0 = s * COLS_PER_SPLIT;
    for (int nb = nb0; nb < nb0 + COLS_PER_SPLIT; nb += TN) {
        __syncthreads();
        for (int idx = t; idx < C * TN; idx += 256) {
            int c = idx / TN, n = idx % TN;
            Fc[c * TN + n] = F[c * HW + nb + n];
        }
        for (int idx = t; idx < TN * CV; idx += 256)
            Vs[idx] = g_V[(b * HW + nb) * CV + idx];
        if (t < TN) r_c[t] = Rj[nb + t];
        __syncthreads();

        float S[8][4];
#pragma unroll
        for (int a = 0; a < 8; a++)
#pragma unroll
            for (int q = 0; q < 4; q++) S[a][q] = 0.f;

#pragma unroll 4
        for (int c = 0; c < C; c++) {
            float4 xr0 = *(const float4*)&Fr[c * TM + i0];
            float4 xr1 = *(const float4*)&Fr[c * TM + i0 + 4];
            float4 xc4 = *(const float4*)&Fc[c * TN + n0];
            float xr[8] = {xr0.x, xr0.y, xr0.z, xr0.w, xr1.x, xr1.y, xr1.z, xr1.w};
            float xcc[4] = {xc4.x, xc4.y, xc4.z, xc4.w};
#pragma unroll
            for (int a = 0; a < 8; a++)
#pragma unroll
                for (int q = 0; q < 4; q++)
                    S[a][q] += xr[a] * xcc[q];
        }
#pragma unroll
        for (int a = 0; a < 8; a++) {
            float ri = r_r[i0 + a];
#pragma unroll
            for (int q = 0; q < 4; q++) {
                float d2 = ri + r_c[n0 + q] - 2.f * S[a][q];
                d2 = fmaxf(d2, 0.f);
                As[(i0 + a) * ASTRIDE + n0 + q] = __expf(-d2 * inv2s);
            }
        }
        __syncthreads();

#pragma unroll 4
        for (int n = 0; n < TN; n++) {
            float a0 = As[(rg * 4 + 0) * ASTRIDE + n];
            float a1 = As[(rg * 4 + 1) * ASTRIDE + n];
            float a2 = As[(rg * 4 + 2) * ASTRIDE + n];
            float a3 = As[(rg * 4 + 3) * ASTRIDE + n];
            float v0 = Vs[n * CV + cq * 3 + 0];
            float v1 = Vs[n * CV + cq * 3 + 1];
            float v2 = Vs[n * CV + cq * 3 + 2];
            O[0][0] += a0 * v0; O[0][1] += a0 * v1; O[0][2] += a0 * v2;
            O[1][0] += a1 * v0; O[1][1] += a1 * v1; O[1][2] += a1 * v2;
            O[2][0] += a2 * v0; O[2][1] += a2 * v1; O[2][2] += a2 * v2;
            O[3][0] += a3 * v0; O[3][1] += a3 * v1; O[3][2] += a3 * v2;
        }
    }

#pragma unroll
    for (int a = 0; a < 4; a++)
#pragma unroll
        for (int q = 0; q < 3; q++)
            g_O[((s * 12 + j * 4 + b) * HW + m0 + rg * 4 + a) * CV + cq * 3 + q] = O[a][q];
}

// ---------------------------------------------------------------------------
// 5) Combine:  att_k = gk * sum_j coef_jk * (O_j_s0 + O_j_s1)[:, k*8:(k+1)*8]
//    out_k = f_k * (att_k @ Wo^T + bo) + edge
// ---------------------------------------------------------------------------
__global__ void combine_kernel(const float* __restrict__ Wo, const float* __restrict__ bo,
                               const float* __restrict__ gammas, float* __restrict__ out)
{
    __shared__ float wo_s[512];   // [64][8]
    __shared__ float bo_s[64];
    int t = threadIdx.x;
    for (int i = t; i < 512; i += 256) wo_s[i] = Wo[i];
    if (t < 64) bo_s[t] = bo[t];
    __syncthreads();

    int k = blockIdx.y, b = blockIdx.z;
    int p = blockIdx.x * 256 + t;

    float g6 = gammas[6], g7 = gammas[7], g8 = gammas[8];
    float c1, c2, c3, gk;
    if (k == 0)      { c1 = g6;       c2 = g7 + 1.f; c3 = g8 + 1.f; gk = gammas[3]; }
    else if (k == 1) { c1 = g6 + 1.f; c2 = g7;       c3 = g8 + 1.f; gk = gammas[4]; }
    else             { c1 = g6 + 1.f; c2 = g7 + 1.f; c3 = g8;       gk = gammas[5]; }

    const int HWCV = HW * CV;
    const float* O0a = g_O + ((0 + b) * HW + p) * CV + k * 8;
    const float* O1a = g_O + ((4 + b) * HW + p) * CV + k * 8;
    const float* O2a = g_O + ((8 + b) * HW + p) * CV + k * 8;
    const float* O0b = O0a + 12 * HWCV;
    const float* O1b = O1a + 12 * HWCV;
    const float* O2b = O2a + 12 * HWCV;
    float att[8];
#pragma unroll
    for (int c = 0; c < 8; c++)
        att[c] = gk * (c1 * (O0a[c] + O0b[c]) + c2 * (O1a[c] + O1b[c]) + c3 * (O2a[c] + O2b[c]));

    float e = g_edge[b * HW + p];
    const float* F = g_f + (k * 4 + b) * C * HW + p;
    float* op = out + k * NPIX + b * C * HW + p;
#pragma unroll 4
    for (int co = 0; co < C; co++) {
        float y = bo_s[co];
#pragma unroll
        for (int c = 0; c < 8; c++) y += wo_s[co * 8 + c] * att[c];
        op[co * HW] = F[co * HW] * y + e;
    }
}

// ---------------------------------------------------------------------------
// Host launcher (graph-capturable: kernel launches only)
// ---------------------------------------------------------------------------
extern "C" void kernel_launch(void* const* d_in, const int* in_sizes, int n_in,
                              void* d_out, int out_size)
{
    const float* x1    = (const float*)d_in[0];
    const float* x2    = (const float*)d_in[1];
    const float* x3    = (const float*)d_in[2];
    const float* Wc1   = (const float*)d_in[3];
    const float* bc1   = (const float*)d_in[4];
    const float* Wc2   = (const float*)d_in[5];
    const float* bc2   = (const float*)d_in[6];
    const float* Wc3   = (const float*)d_in[7];
    const float* bc3   = (const float*)d_in[8];
    const float* bnf_g = (const float*)d_in[9];
    const float* bnf_b = (const float*)d_in[10];
    const float* bnf_m = (const float*)d_in[11];
    const float* bnf_v = (const float*)d_in[12];
    const float* Wm    = (const float*)d_in[13];
    const float* bm    = (const float*)d_in[14];
    const float* bnm_g = (const float*)d_in[15];
    const float* bnm_b = (const float*)d_in[16];
    const float* bnm_m = (const float*)d_in[17];
    const float* bnm_v = (const float*)d_in[18];
    const float* Wv    = (const float*)d_in[19];
    const float* bv    = (const float*)d_in[20];
    const float* Wo    = (const float*)d_in[21];
    const float* bo    = (const float*)d_in[22];
    const float* gam   = (const float*)d_in[23];
    float* out = (float*)d_out;

    float *buf1, *buf2, *fbase;
    cudaGetSymbolAddress((void**)&buf1, g_buf1);
    cudaGetSymbolAddress((void**)&buf2, g_buf2);
    cudaGetSymbolAddress((void**)&fbase, g_f);

    const size_t ATTN_SMEM = (size_t)(C * TM + C * TN + TM * ASTRIDE + TN * CV + TM + TN) * 4;
    cudaFuncSetAttribute(attn_kernel, cudaFuncAttributeMaxDynamicSharedMemorySize, (int)ATTN_SMEM);

    prep_kernel<<<1, 576>>>(bc1, bc2, bc3, bnf_g, bnf_b, bnf_m, bnf_v,
                            bm, bnm_g, bnm_b, bnm_m, bnm_v);
    edge_kernel<<<(B * HW + 255) / 256, 256>>>(x3);

    dim3 cgrid(12, 4, 12);
    conv1_kernel<<<cgrid, 128>>>(x1, x2, x3, Wc1, Wc2, Wc3, buf1);
    convm_kernel<<<cgrid, 128>>>(buf1, Wm, 0, buf2);
    convm_kernel<<<cgrid, 128>>>(buf2, Wm, 1, fbase);

    valr_kernel<<<dim3(9, 3, B), 256>>>(Wv, bv);
    attn_kernel<<<dim3((HW / TM) * NSPLIT, 3, B), 256, ATTN_SMEM>>>(gam);
    combine_kernel<<<dim3(9, 3, B), 256>>>(Wo, bo, gam, out);
}

// round 4
// speedup vs baseline: 2.1232x; 1.5478x over previous
#include <cuda_runtime.h>
#include <cuda_bf16.h>
#include <math.h>
#include <stdint.h>

// ---------------------------------------------------------------------------
// Problem constants
// ---------------------------------------------------------------------------
#define B 4
#define C 64
#define IMGH 48
#define IMGW 48
#define HW 2304                 // 48*48
#define NPIX 589824             // B*C*HW
#define CV 24                   // 3 * (C/8) value columns
#define NSPLIT 4

// ---------------------------------------------------------------------------
// Device scratch (no cudaMalloc allowed)
// ---------------------------------------------------------------------------
__device__ float g_buf1[3 * NPIX];
__device__ float g_buf2[3 * NPIX];
__device__ float g_f[3 * NPIX];                 // [3][B][64][HW]
__device__ float g_r[12 * HW];                  // [3][B][2304]
__device__ float g_V[B * CV * HW];              // [B][24][HW]  (transposed!)
__device__ float g_O[NSPLIT * 12 * HW * CV];    // [split][3][B][2304][24]
__device__ float g_edge[B * HW];
__device__ float g_scale[9 * 64];
__device__ float g_shift[9 * 64];

// ---------------------------------------------------------------------------
// mma / ldmatrix helpers
// ---------------------------------------------------------------------------
__device__ __forceinline__ void ldsm_x4(uint32_t& r0, uint32_t& r1, uint32_t& r2,
                                        uint32_t& r3, uint32_t addr)
{
    asm volatile("ldmatrix.sync.aligned.m8n8.x4.shared.b16 {%0,%1,%2,%3}, [%4];"
                 : "=r"(r0), "=r"(r1), "=r"(r2), "=r"(r3) : "r"(addr));
}

__device__ __forceinline__ void mma16816(float4& d, const uint32_t a[4],
                                         uint32_t b0, uint32_t b1)
{
    asm volatile(
        "mma.sync.aligned.m16n8k16.row.col.f32.bf16.bf16.f32 "
        "{%0,%1,%2,%3}, {%4,%5,%6,%7}, {%8,%9}, {%0,%1,%2,%3};\n"
        : "+f"(d.x), "+f"(d.y), "+f"(d.z), "+f"(d.w)
        : "r"(a[0]), "r"(a[1]), "r"(a[2]), "r"(a[3]), "r"(b0), "r"(b1));
}

__device__ __forceinline__ void mma16808(float4& d, uint32_t a0, uint32_t a1, uint32_t b0)
{
    asm volatile(
        "mma.sync.aligned.m16n8k8.row.col.f32.bf16.bf16.f32 "
        "{%0,%1,%2,%3}, {%4,%5}, {%6}, {%0,%1,%2,%3};\n"
        : "+f"(d.x), "+f"(d.y), "+f"(d.z), "+f"(d.w)
        : "r"(a0), "r"(a1), "r"(b0));
}

// pack (x -> low half, y -> high half) bf16 hi parts and residual lo parts
__device__ __forceinline__ void split_pair(float x, float y, uint32_t& hi, uint32_t& lo)
{
    __nv_bfloat16 hx = __float2bfloat16(x);
    __nv_bfloat16 hy = __float2bfloat16(y);
    hi = (uint32_t)__bfloat16_as_ushort(hx) | ((uint32_t)__bfloat16_as_ushort(hy) << 16);
    __nv_bfloat16 lx = __float2bfloat16(x - __bfloat162float(hx));
    __nv_bfloat16 ly = __float2bfloat16(y - __bfloat162float(hy));
    lo = (uint32_t)__bfloat16_as_ushort(lx) | ((uint32_t)__bfloat16_as_ushort(ly) << 16);
}

// ---------------------------------------------------------------------------
// 0) Fold conv bias + BN into per-channel scale/shift
// ---------------------------------------------------------------------------
__global__ void prep_kernel(const float* __restrict__ bc1, const float* __restrict__ bc2,
                            const float* __restrict__ bc3,
                            const float* __restrict__ bnf_g, const float* __restrict__ bnf_b,
                            const float* __restrict__ bnf_m, const float* __restrict__ bnf_v,
                            const float* __restrict__ bm,
                            const float* __restrict__ bnm_g, const float* __restrict__ bnm_b,
                            const float* __restrict__ bnm_m, const float* __restrict__ bnm_v)
{
    int t = threadIdx.x;
    if (t >= 576) return;
    int bi = t >> 6, c = t & 63;
    float bias, g, be, m, v;
    if (bi < 3) {
        bias = (bi == 0) ? bc1[c] : (bi == 1) ? bc2[c] : bc3[c];
        g = bnf_g[bi * 64 + c]; be = bnf_b[bi * 64 + c];
        m = bnf_m[bi * 64 + c]; v = bnf_v[bi * 64 + c];
    } else {
        int r = bi - 3;
        bias = bm[r * 64 + c];
        g = bnm_g[r * 64 + c]; be = bnm_b[r * 64 + c];
        m = bnm_m[r * 64 + c]; v = bnm_v[r * 64 + c];
    }
    float s = g * rsqrtf(v + 1e-5f);
    g_scale[t] = s;
    g_shift[t] = (bias - m) * s + be;
}

// ---------------------------------------------------------------------------
// 1) Sobel edge on raw x3
// ---------------------------------------------------------------------------
__global__ void edge_kernel(const float* __restrict__ x3)
{
    int idx = blockIdx.x * 256 + threadIdx.x;
    if (idx >= B * HW) return;
    int b = idx / HW, p = idx % HW;
    int h = p / IMGW, w = p % IMGW;
    const float* X = x3 + b * HW;
    float ex = 0.f, ey = 0.f;
    const float KX[9] = {-1.f, 0.f, 1.f, -2.f, 0.f, 2.f, -1.f, 0.f, 1.f};
    const float KY[9] = {-1.f, -2.f, -1.f, 0.f, 0.f, 0.f, 1.f, 2.f, 1.f};
#pragma unroll
    for (int kh = 0; kh < 3; kh++) {
        int gh = h + kh - 1;
        if (gh < 0 || gh >= IMGH) continue;
#pragma unroll
        for (int kw = 0; kw < 3; kw++) {
            int gw = w + kw - 1;
            if (gw < 0 || gw >= IMGW) continue;
            float xv = X[gh * IMGW + gw];
            ex += xv * KX[kh * 3 + kw];
            ey += xv * KY[kh * 3 + kw];
        }
    }
    g_edge[idx] = sqrtf(ex * ex + ey * ey);
}

// ---------------------------------------------------------------------------
// 2) 3x3 conv (SAME) + folded BN + LeakyReLU(0.01)
// ---------------------------------------------------------------------------
#define CIN_CHUNK 16
__device__ __forceinline__ void conv_body(const float* __restrict__ in,
                                          const float* __restrict__ W,
                                          int Cin, int bn_idx, int b,
                                          float* __restrict__ out)
{
    __shared__ float in_s[CIN_CHUNK][6][50];
    __shared__ __align__(16) float w_s[CIN_CHUNK * 9 * 16];

    const int strip = blockIdx.x, cog = blockIdx.y;
    const int r0 = strip * 4;
    const int t = threadIdx.x;
    const int cg = t & 3;
    const int pg = t >> 2;
    const int prow = pg >> 3;
    const int pcol0 = (pg & 7) * 6;
    const int cg4 = cg * 4;

    float acc[6][4];
#pragma unroll
    for (int i = 0; i < 6; i++)
#pragma unroll
        for (int j = 0; j < 4; j++) acc[i][j] = 0.f;

    for (int c0 = 0; c0 < Cin; c0 += CIN_CHUNK) {
        int cc = min(CIN_CHUNK, Cin - c0);
        for (int idx = t; idx < cc * 300; idx += 128) {
            int ci = idx / 300;
            int rem = idx % 300;
            int rr = rem / 50, ccol = rem % 50;
            int gr = r0 + rr - 1, gcol = ccol - 1;
            float v = 0.f;
            if (gr >= 0 && gr < IMGH && gcol >= 0 && gcol < IMGW)
                v = in[((b * Cin + c0 + ci) * IMGH + gr) * IMGW + gcol];
            in_s[ci][rr][ccol] = v;
        }
        for (int idx = t; idx < cc * 9 * 16; idx += 128) {
            int co = idx & 15;
            int tmp = idx >> 4;
            int tap = tmp % 9;
            int ci = tmp / 9;
            w_s[idx] = W[((cog * 16 + co) * Cin + c0 + ci) * 9 + tap];
        }
        __syncthreads();

        for (int ci = 0; ci < cc; ++ci) {
            float x[3][8];
#pragma unroll
            for (int rr = 0; rr < 3; rr++)
#pragma unroll
                for (int k = 0; k < 8; k++)
                    x[rr][k] = in_s[ci][prow + rr][pcol0 + k];
#pragma unroll
            for (int tr = 0; tr < 3; tr++) {
#pragma unroll
                for (int tc = 0; tc < 3; tc++) {
                    float4 w4 = *(const float4*)&w_s[(ci * 9 + tr * 3 + tc) * 16 + cg4];
#pragma unroll
                    for (int px = 0; px < 6; px++) {
                        float xv = x[tr][px + tc];
                        acc[px][0] += xv * w4.x;
                        acc[px][1] += xv * w4.y;
                        acc[px][2] += xv * w4.z;
                        acc[px][3] += xv * w4.w;
                    }
                }
            }
        }
        __syncthreads();
    }

#pragma unroll
    for (int co = 0; co < 4; co++) {
        int coo = cog * 16 + cg4 + co;
        float s = g_scale[bn_idx * 64 + coo];
        float sh = g_shift[bn_idx * 64 + coo];
#pragma unroll
        for (int px = 0; px < 6; px++) {
            float y = acc[px][co] * s + sh;
            y = (y > 0.f) ? y : 0.01f * y;
            out[((b * C + coo) * IMGH + r0 + prow) * IMGW + pcol0 + px] = y;
        }
    }
}

__global__ __launch_bounds__(128) void conv1_kernel(const float* __restrict__ x1,
                                                    const float* __restrict__ x2,
                                                    const float* __restrict__ x3,
                                                    const float* __restrict__ W1,
                                                    const float* __restrict__ W2,
                                                    const float* __restrict__ W3,
                                                    float* __restrict__ out)
{
    int z = blockIdx.z;
    int b = z & 3, br = z >> 2;
    const float* in = (br == 0) ? x1 : (br == 1) ? x2 : x3;
    const float* W  = (br == 0) ? W1 : (br == 1) ? W2 : W3;
    int Cin         = (br == 0) ? 144 : (br == 1) ? 21 : 1;
    conv_body(in, W, Cin, br, b, out + br * NPIX);
}

__global__ __launch_bounds__(128) void convm_kernel(const float* __restrict__ inbase,
                                                    const float* __restrict__ Wm,
                                                    int layer,
                                                    float* __restrict__ outbase)
{
    int z = blockIdx.z;
    int b = z & 3, br = z >> 2;
    int wi = br * 2 + layer;
    const int WMROW = 64 * 64 * 9;
    conv_body(inbase + br * NPIX, Wm + wi * WMROW, 64, 3 + wi, b, outbase + br * NPIX);
}

// ---------------------------------------------------------------------------
// 3) squared norms + 1x1 value projection, g_V stored [B][24][HW]
// ---------------------------------------------------------------------------
__global__ void valr_kernel(const float* __restrict__ Wv, const float* __restrict__ bv)
{
    __shared__ float wv_s[512];   // [8][64]
    int t = threadIdx.x;
    int j = blockIdx.y, b = blockIdx.z;
    for (int i = t; i < 512; i += 256) wv_s[i] = Wv[i];
    __syncthreads();

    int p = blockIdx.x * 256 + t;
    const float* F = g_f + (j * 4 + b) * C * HW + p;
    float r = 0.f;
    float v[8] = {0, 0, 0, 0, 0, 0, 0, 0};
#pragma unroll 8
    for (int c = 0; c < C; c++) {
        float x = F[c * HW];
        r += x * x;
#pragma unroll
        for (int cv = 0; cv < 8; cv++) v[cv] += wv_s[cv * 64 + c] * x;
    }
    g_r[(j * 4 + b) * HW + p] = r;
#pragma unroll
    for (int cv = 0; cv < 8; cv++)
        g_V[(b * CV + j * 8 + cv) * HW + p] = v[cv] + bv[cv];
}

// ---------------------------------------------------------------------------
// 4) Tensor-core fused similarity-attention (bf16 split precision)
//    S = F^T F (4-pass split, mma m16n8k16), exp on fragments,
//    O += exp(S) @ V (3-pass split, mma m16n8k8)
//    Block: 256 thr (8 warps: 4 m-groups x 2 n-groups). Tile TM=128 x TN=64.
// ---------------------------------------------------------------------------
#define TM 128
#define TN 64
#define FSTR 72
#define VSTR 72
#define COLS_PER_SPLIT (HW / NSPLIT)

#define OFF_FRH 0
#define OFF_FRL (OFF_FRH + TM * FSTR * 2)            // 18432
#define OFF_FCH (OFF_FRL + TM * FSTR * 2)            // 36864
#define OFF_FCL (OFF_FCH + TN * FSTR * 2)            // 46080
#define OFF_VSTH (OFF_FCL + TN * FSTR * 2)           // 55296
#define OFF_VSTL (OFF_VSTH + CV * VSTR * 2)          // 58752
#define OFF_RR  (OFF_VSTL + CV * VSTR * 2)           // 62208
#define OFF_RC  (OFF_RR + TM * 4)                    // 62720
#define ATTN_SMEM_BYTES (OFF_RC + TN * 4)            // 62976

__global__ __launch_bounds__(256, 2) void attn_kernel(const float* __restrict__ gammas)
{
    extern __shared__ char sm[];
    __nv_bfloat16* FrH = (__nv_bfloat16*)(sm + OFF_FRH);
    __nv_bfloat16* FrL = (__nv_bfloat16*)(sm + OFF_FRL);
    __nv_bfloat16* FcH = (__nv_bfloat16*)(sm + OFF_FCH);
    __nv_bfloat16* FcL = (__nv_bfloat16*)(sm + OFF_FCL);
    __nv_bfloat16* VsH = (__nv_bfloat16*)(sm + OFF_VSTH);
    __nv_bfloat16* VsL = (__nv_bfloat16*)(sm + OFF_VSTL);
    float* r_r = (float*)(sm + OFF_RR);
    float* r_c = (float*)(sm + OFF_RC);
    uint32_t sb = (uint32_t)__cvta_generic_to_shared(sm);

    const int s    = blockIdx.x & (NSPLIT - 1);
    const int tile = blockIdx.x >> 2;                 // log2(NSPLIT)=2
    const int j = blockIdx.y, bb = blockIdx.z;
    const int m0 = tile * TM;
    const int t = threadIdx.x;
    const int warp = t >> 5, lane = t & 31;
    const int mg = warp >> 1, ng = warp & 1;
    const int m0w = mg * 32, n0w = ng * 32;
    const int g = lane >> 2, qp = lane & 3;

    const float* F  = g_f + (j * 4 + bb) * C * HW;
    const float* Rj = g_r + (j * 4 + bb) * HW;

    float sg = gammas[j];
    float inv2s = 1.0f / (2.0f * sg * sg);

    // ---- stage Fr (hi/lo) and r_r once ----
    for (int idx = t; idx < TM * C; idx += 256) {
        int i = idx & (TM - 1);
        int c = idx >> 7;
        float x = F[c * HW + m0 + i];
        __nv_bfloat16 h = __float2bfloat16(x);
        FrH[i * FSTR + c] = h;
        FrL[i * FSTR + c] = __float2bfloat16(x - __bfloat162float(h));
    }
    if (t < TM) r_r[t] = Rj[m0 + t];
    __syncthreads();

    float rr0[2], rr1[2];
#pragma unroll
    for (int mt = 0; mt < 2; mt++) {
        rr0[mt] = r_r[m0w + mt * 16 + g];
        rr1[mt] = r_r[m0w + mt * 16 + g + 8];
    }

    // ldmatrix lane addresses
    const int a_r = m0w + (lane & 7) + ((lane >> 3) & 1) * 8;
    const int a_c = ((lane >> 4) & 1) * 8;
    const uint32_t aH0 = sb + OFF_FRH + (uint32_t)(a_r * FSTR + a_c) * 2;
    const uint32_t aL0 = sb + OFF_FRL + (uint32_t)(a_r * FSTR + a_c) * 2;
    const int b_r = n0w + (lane & 7) + ((lane >> 4) & 1) * 8;
    const int b_c = ((lane >> 3) & 1) * 8;
    const uint32_t bH0 = sb + OFF_FCH + (uint32_t)(b_r * FSTR + b_c) * 2;
    const uint32_t bL0 = sb + OFF_FCL + (uint32_t)(b_r * FSTR + b_c) * 2;
    // V b-frag scalar address (bytes, generic pointer arithmetic on sm)
    const int vbase = ((lane >> 2) * VSTR + n0w + qp * 2) * 2;

    float4 O[2][3];
#pragma unroll
    for (int mt = 0; mt < 2; mt++)
#pragma unroll
        for (int vt = 0; vt < 3; vt++) O[mt][vt] = make_float4(0.f, 0.f, 0.f, 0.f);

    const int nb0 = s * COLS_PER_SPLIT;
    for (int nb = nb0; nb < nb0 + COLS_PER_SPLIT; nb += TN) {
        __syncthreads();
        // stage Fc (hi/lo)
        for (int idx = t; idx < TN * C; idx += 256) {
            int n = idx & (TN - 1);
            int c = idx >> 6;
            float x = F[c * HW + nb + n];
            __nv_bfloat16 h = __float2bfloat16(x);
            FcH[n * FSTR + c] = h;
            FcL[n * FSTR + c] = __float2bfloat16(x - __bfloat162float(h));
        }
        // stage V chunk transposed (hi/lo): Vs[vc][n]
        for (int idx = t; idx < CV * TN; idx += 256) {
            int n = idx & (TN - 1);
            int vc = idx >> 6;
            float x = g_V[(bb * CV + vc) * HW + nb + n];
            __nv_bfloat16 h = __float2bfloat16(x);
            VsH[vc * VSTR + n] = h;
            VsL[vc * VSTR + n] = __float2bfloat16(x - __bfloat162float(h));
        }
        if (t < TN) r_c[t] = Rj[nb + t];
        __syncthreads();

        // ---- Gram: acc = Fr^T Fc (4-pass split bf16: HH, HL, LH, LL) ----
        float4 acc[2][4];
#pragma unroll
        for (int mt = 0; mt < 2; mt++)
#pragma unroll
            for (int nt = 0; nt < 4; nt++) acc[mt][nt] = make_float4(0.f, 0.f, 0.f, 0.f);

#pragma unroll
        for (int kt = 0; kt < 4; kt++) {
            uint32_t AH[2][4], AL[2][4], BH[2][4], BL[2][4];
            ldsm_x4(AH[0][0], AH[0][1], AH[0][2], AH[0][3], aH0 + kt * 32);
            ldsm_x4(AH[1][0], AH[1][1], AH[1][2], AH[1][3], aH0 + kt * 32 + 16 * FSTR * 2);
            ldsm_x4(AL[0][0], AL[0][1], AL[0][2], AL[0][3], aL0 + kt * 32);
            ldsm_x4(AL[1][0], AL[1][1], AL[1][2], AL[1][3], aL0 + kt * 32 + 16 * FSTR * 2);
            ldsm_x4(BH[0][0], BH[0][1], BH[0][2], BH[0][3], bH0 + kt * 32);
            ldsm_x4(BH[1][0], BH[1][1], BH[1][2], BH[1][3], bH0 + kt * 32 + 16 * FSTR * 2);
            ldsm_x4(BL[0][0], BL[0][1], BL[0][2], BL[0][3], bL0 + kt * 32);
            ldsm_x4(BL[1][0], BL[1][1], BL[1][2], BL[1][3], bL0 + kt * 32 + 16 * FSTR * 2);
#pragma unroll
            for (int mt = 0; mt < 2; mt++) {
#pragma unroll
                for (int nt = 0; nt < 4; nt++) {
                    int np = nt >> 1, e = (nt & 1) * 2;
                    mma16816(acc[mt][nt], AH[mt], BH[np][e], BH[np][e + 1]);
                    mma16816(acc[mt][nt], AH[mt], BL[np][e], BL[np][e + 1]);
                    mma16816(acc[mt][nt], AL[mt], BH[np][e], BH[np][e + 1]);
                    mma16816(acc[mt][nt], AL[mt], BL[np][e], BL[np][e + 1]);
                }
            }
        }

        // ---- d2 -> exp (on fragments); col index includes warp offset n0w ----
#pragma unroll
        for (int nt = 0; nt < 4; nt++) {
            float rc0 = r_c[n0w + nt * 8 + qp * 2];
            float rc1 = r_c[n0w + nt * 8 + qp * 2 + 1];
#pragma unroll
            for (int mt = 0; mt < 2; mt++) {
                float4& a4 = acc[mt][nt];
                a4.x = __expf(-fmaxf(rr0[mt] + rc0 - 2.f * a4.x, 0.f) * inv2s);
                a4.y = __expf(-fmaxf(rr0[mt] + rc1 - 2.f * a4.y, 0.f) * inv2s);
                a4.z = __expf(-fmaxf(rr1[mt] + rc0 - 2.f * a4.z, 0.f) * inv2s);
                a4.w = __expf(-fmaxf(rr1[mt] + rc1 - 2.f * a4.w, 0.f) * inv2s);
            }
        }

        // ---- O += A @ V (k8 mma, accumulator reused as A operand) ----
#pragma unroll
        for (int kt = 0; kt < 4; kt++) {
            uint32_t ah0[2], ah1[2], al0[2], al1[2];
#pragma unroll
            for (int mt = 0; mt < 2; mt++) {
                split_pair(acc[mt][kt].x, acc[mt][kt].y, ah0[mt], al0[mt]);
                split_pair(acc[mt][kt].z, acc[mt][kt].w, ah1[mt], al1[mt]);
            }
#pragma unroll
            for (int vt = 0; vt < 3; vt++) {
                int vo = vbase + (vt * 8 * VSTR + kt * 8) * 2;
                uint32_t bh = *(const uint32_t*)(sm + OFF_VSTH + vo);
                uint32_t bl = *(const uint32_t*)(sm + OFF_VSTL + vo);
#pragma unroll
                for (int mt = 0; mt < 2; mt++) {
                    mma16808(O[mt][vt], ah0[mt], ah1[mt], bh);
                    mma16808(O[mt][vt], ah0[mt], ah1[mt], bl);
                    mma16808(O[mt][vt], al0[mt], al1[mt], bh);
                }
            }
        }
    }

    // ---- reduce the two n-groups and store ----
    __syncthreads();
    float* Osh = (float*)sm;    // 128*24 floats = 12 KB, Fr region is dead
    if (ng == 1) {
#pragma unroll
        for (int mt = 0; mt < 2; mt++)
#pragma unroll
            for (int vt = 0; vt < 3; vt++) {
                int r0 = m0w + mt * 16 + g;
                int c0 = vt * 8 + qp * 2;
                Osh[r0 * CV + c0] = O[mt][vt].x;
                Osh[r0 * CV + c0 + 1] = O[mt][vt].y;
                Osh[(r0 + 8) * CV + c0] = O[mt][vt].z;
                Osh[(r0 + 8) * CV + c0 + 1] = O[mt][vt].w;
            }
    }
    __syncthreads();
    if (ng == 0) {
        float* dst = g_O + ((size_t)((s * 12 + j * 4 + bb)) * HW + m0) * CV;
#pragma unroll
        for (int mt = 0; mt < 2; mt++)
#pragma unroll
            for (int vt = 0; vt < 3; vt++) {
                int r0 = m0w + mt * 16 + g;
                int c0 = vt * 8 + qp * 2;
                dst[r0 * CV + c0]           = O[mt][vt].x + Osh[r0 * CV + c0];
                dst[r0 * CV + c0 + 1]       = O[mt][vt].y + Osh[r0 * CV + c0 + 1];
                dst[(r0 + 8) * CV + c0]     = O[mt][vt].z + Osh[(r0 + 8) * CV + c0];
                dst[(r0 + 8) * CV + c0 + 1] = O[mt][vt].w + Osh[(r0 + 8) * CV + c0 + 1];
            }
    }
}

// ---------------------------------------------------------------------------
// 5) Combine: sum NSPLIT partial O slabs, mix, 1x1 out conv, gate, add edge
// ---------------------------------------------------------------------------
__global__ void combine_kernel(const float* __restrict__ Wo, const float* __restrict__ bo,
                               const float* __restrict__ gammas, float* __restrict__ out)
{
    __shared__ float wo_s[512];   // [64][8]
    __shared__ float bo_s[64];
    int t = threadIdx.x;
    for (int i = t; i < 512; i += 256) wo_s[i] = Wo[i];
    if (t < 64) bo_s[t] = bo[t];
    __syncthreads();

    int k = blockIdx.y, b = blockIdx.z;
    int p = blockIdx.x * 256 + t;

    float g6 = gammas[6], g7 = gammas[7], g8 = gammas[8];
    float c1, c2, c3, gk;
    if (k == 0)      { c1 = g6;       c2 = g7 + 1.f; c3 = g8 + 1.f; gk = gammas[3]; }
    else if (k == 1) { c1 = g6 + 1.f; c2 = g7;       c3 = g8 + 1.f; gk = gammas[4]; }
    else             { c1 = g6 + 1.f; c2 = g7 + 1.f; c3 = g8;       gk = gammas[5]; }

    const size_t SLAB = (size_t)12 * HW * CV;
    float s0[8] = {0}, s1[8] = {0}, s2[8] = {0};
#pragma unroll
    for (int sp = 0; sp < NSPLIT; sp++) {
        const float* O0 = g_O + sp * SLAB + ((size_t)(0 + b) * HW + p) * CV + k * 8;
        const float* O1 = g_O + sp * SLAB + ((size_t)(4 + b) * HW + p) * CV + k * 8;
        const float* O2 = g_O + sp * SLAB + ((size_t)(8 + b) * HW + p) * CV + k * 8;
#pragma unroll
        for (int c = 0; c < 8; c++) { s0[c] += O0[c]; s1[c] += O1[c]; s2[c] += O2[c]; }
    }
    float att[8];
#pragma unroll
    for (int c = 0; c < 8; c++)
        att[c] = gk * (c1 * s0[c] + c2 * s1[c] + c3 * s2[c]);

    float e = g_edge[b * HW + p];
    const float* F = g_f + (k * 4 + b) * C * HW + p;
    float* op = out + k * NPIX + b * C * HW + p;
#pragma unroll 4
    for (int co = 0; co < C; co++) {
        float y = bo_s[co];
#pragma unroll
        for (int c = 0; c < 8; c++) y += wo_s[co * 8 + c] * att[c];
        op[co * HW] = F[co * HW] * y + e;
    }
}

// ---------------------------------------------------------------------------
// Host launcher (graph-capturable)
// ---------------------------------------------------------------------------
extern "C" void kernel_launch(void* const* d_in, const int* in_sizes, int n_in,
                              void* d_out, int out_size)
{
    const float* x1    = (const float*)d_in[0];
    const float* x2    = (const float*)d_in[1];
    const float* x3    = (const float*)d_in[2];
    const float* Wc1   = (const float*)d_in[3];
    const float* bc1   = (const float*)d_in[4];
    const float* Wc2   = (const float*)d_in[5];
    const float* bc2   = (const float*)d_in[6];
    const float* Wc3   = (const float*)d_in[7];
    const float* bc3   = (const float*)d_in[8];
    const float* bnf_g = (const float*)d_in[9];
    const float* bnf_b = (const float*)d_in[10];
    const float* bnf_m = (const float*)d_in[11];
    const float* bnf_v = (const float*)d_in[12];
    const float* Wm    = (const float*)d_in[13];
    const float* bm    = (const float*)d_in[14];
    const float* bnm_g = (const float*)d_in[15];
    const float* bnm_b = (const float*)d_in[16];
    const float* bnm_m = (const float*)d_in[17];
    const float* bnm_v = (const float*)d_in[18];
    const float* Wv    = (const float*)d_in[19];
    const float* bv    = (const float*)d_in[20];
    const float* Wo    = (const float*)d_in[21];
    const float* bo    = (const float*)d_in[22];
    const float* gam   = (const float*)d_in[23];
    float* out = (float*)d_out;

    float *buf1, *buf2, *fbase;
    cudaGetSymbolAddress((void**)&buf1, g_buf1);
    cudaGetSymbolAddress((void**)&buf2, g_buf2);
    cudaGetSymbolAddress((void**)&fbase, g_f);

    cudaFuncSetAttribute(attn_kernel, cudaFuncAttributeMaxDynamicSharedMemorySize,
                         ATTN_SMEM_BYTES);

    prep_kernel<<<1, 576>>>(bc1, bc2, bc3, bnf_g, bnf_b, bnf_m, bnf_v,
                            bm, bnm_g, bnm_b, bnm_m, bnm_v);
    edge_kernel<<<(B * HW + 255) / 256, 256>>>(x3);

    dim3 cgrid(12, 4, 12);
    conv1_kernel<<<cgrid, 128>>>(x1, x2, x3, Wc1, Wc2, Wc3, buf1);
    convm_kernel<<<cgrid, 128>>>(buf1, Wm, 0, buf2);
    convm_kernel<<<cgrid, 128>>>(buf2, Wm, 1, fbase);

    valr_kernel<<<dim3(9, 3, B), 256>>>(Wv, bv);
    attn_kernel<<<dim3((HW / TM) * NSPLIT, 3, B), 256, ATTN_SMEM_BYTES>>>(gam);
    combine_kernel<<<dim3(9, 3, B), 256>>>(Wo, bo, gam, out);
}